// round 1
// baseline (speedup 1.0000x reference)
#include <cuda_runtime.h>
#include <cuda_bf16.h>

// Problem constants
#define B_ 32
#define L_ 128
#define D_ 48
#define R_ 64
// ref_r = linspace(0, 48, 64) -> r * 48/63

// Partial-sum scratch: 16 slices (4 L-splits x 4 l-groups) of (B,R,D)
__device__ float g_scratch[16 * B_ * R_ * D_];

__global__ __launch_bounds__(192) void alnn_main(
    const float* __restrict__ X, const float* __restrict__ T,
    const float* __restrict__ M, const float* __restrict__ DT,
    const float* __restrict__ P, const float* __restrict__ alpha,
    const float* __restrict__ w_t, const float* __restrict__ b_t,
    const float* __restrict__ w_v)
{
    // Grid: 128 CTAs = 4 batch-groups x 8 r-groups x 4 L-splits
    const int c  = blockIdx.x;
    const int ls = c & 3;          // L split (32 l's each)
    const int rg = (c >> 2) & 7;   // r group (8 r's)
    const int bg = c >> 5;         // batch group (8 b's)

    const int tid = threadIdx.x;   // 192 = 48 d x 4 l-groups
    const int d = tid % D_;
    const int g = tid / D_;        // 0..3, 8 l's each
    const int b0 = bg * 8;
    const int r0 = rg * 8;
    const int l0 = ls * 32 + g * 8;

    // Per-r constants (alpha load is warp-uniform -> cheap)
    float a2[8], refr[8];
#pragma unroll
    for (int ri = 0; ri < 8; ri++) {
        int r = r0 + ri;
        a2[ri]   = fmaxf(alpha[r], 0.0f) * 1.4426950408889634f; // relu(alpha)*log2(e)
        refr[ri] = (float)r * (48.0f / 63.0f);
    }

    float acc[8][8];
#pragma unroll
    for (int bi = 0; bi < 8; bi++)
#pragma unroll
        for (int ri = 0; ri < 8; ri++) acc[bi][ri] = 0.0f;

#pragma unroll 1
    for (int j = 0; j < 8; j++) {
        const int l = l0 + j;

        // Load inputs for 8 batches at (l,d) into registers (coalesced over d)
        float xv[8], tv[8], mv[8], dtv[8], pv[8];
#pragma unroll
        for (int bi = 0; bi < 8; bi++) {
            const int idx = ((b0 + bi) * L_ + l) * D_ + d;
            xv[bi]  = X[idx];
            tv[bi]  = T[idx];
            mv[bi]  = M[idx];
            dtv[bi] = DT[idx];
            pv[bi]  = P[idx];
        }

        const int wbase = (r0 * L_ + l) * D_ + d;
#pragma unroll
        for (int ri = 0; ri < 8; ri++) {
            const int wi = wbase + ri * (L_ * D_);
            const float* wt = w_t + (size_t)wi * 5;
            const float w0 = wt[0], w1 = wt[1], w2 = wt[2], w3 = wt[3], w4 = wt[4];
            const float bt5 = 5.0f * b_t[wi];   // b_t broadcast over 5-axis -> x5
            const float wv  = w_v[wi];
            const float aa = a2[ri], rr = refr[ri];
#pragma unroll
            for (int bi = 0; bi < 8; bi++) {
                const float dd  = fabsf(tv[bi] - rr);
                const float arg = -aa * dd;
                float k;
                asm("ex2.approx.ftz.f32 %0, %1;" : "=f"(k) : "f"(arg));
                const float inten = fmaxf(xv[bi] * k, 0.0f);   // relu(x*kernel)
                float s = fmaf(w0, xv[bi], bt5);
                s = fmaf(w1, inten,  s);
                s = fmaf(w2, mv[bi], s);
                s = fmaf(w3, dtv[bi], s);
                s = fmaf(w4, pv[bi], s);
                const float h = fmaxf(s, 0.0f);
                acc[bi][ri] = fmaf(wv, h, acc[bi][ri]);
            }
        }
    }

    // Write partials: slice = which (L-split, l-group) this is
    const int slice = ls * 4 + g;
    float* sp = g_scratch + (size_t)slice * (B_ * R_ * D_);
#pragma unroll
    for (int bi = 0; bi < 8; bi++)
#pragma unroll
        for (int ri = 0; ri < 8; ri++)
            sp[(((b0 + bi) * R_) + (r0 + ri)) * D_ + d] = acc[bi][ri];
}

__global__ void alnn_finalize(const float* __restrict__ b_v, float* __restrict__ out)
{
    const int i = blockIdx.x * blockDim.x + threadIdx.x;
    if (i >= B_ * R_ * D_) return;
    const int d = i % D_;
    const int r = (i / D_) % R_;
    // b_v shape (R,1,D) broadcast over L then summed -> x128
    float s = 128.0f * b_v[r * D_ + d];
#pragma unroll
    for (int k = 0; k < 16; k++)
        s += g_scratch[k * (B_ * R_ * D_) + i];
    out[i] = fmaxf(s, 0.0f);
}

extern "C" void kernel_launch(void* const* d_in, const int* in_sizes, int n_in,
                              void* d_out, int out_size)
{
    const float* X     = (const float*)d_in[0];
    const float* T     = (const float*)d_in[1];
    const float* M     = (const float*)d_in[2];
    const float* DT    = (const float*)d_in[3];
    const float* P     = (const float*)d_in[4];
    const float* alpha = (const float*)d_in[5];
    const float* w_t   = (const float*)d_in[6];
    const float* b_t   = (const float*)d_in[7];
    const float* w_v   = (const float*)d_in[8];
    const float* b_v   = (const float*)d_in[9];
    float* out = (float*)d_out;

    alnn_main<<<128, 192>>>(X, T, M, DT, P, alpha, w_t, b_t, w_v);

    const int n = B_ * R_ * D_;
    alnn_finalize<<<(n + 255) / 256, 256>>>(b_v, out);
}

// round 2
// speedup vs baseline: 1.0931x; 1.0931x over previous
#include <cuda_runtime.h>

#define B_ 32
#define L_ 128
#define D_ 48
#define R_ 64
#define OUTSZ (B_*R_*D_)   // 98304

typedef unsigned long long ull;

// 8 partial slices (one per L-split) of (B,R,D)
__device__ float g_scratch[8 * OUTSZ];

#define PACK2(dst, lo, hi) \
    asm("mov.b64 %0, {%1, %2};" : "=l"(dst) : "r"(__float_as_uint(lo)), "r"(__float_as_uint(hi)))
#define UNPACK2(lo, hi, src) do { unsigned _a, _b; \
    asm("mov.b64 {%0, %1}, %2;" : "=r"(_a), "=r"(_b) : "l"(src)); \
    lo = __uint_as_float(_a); hi = __uint_as_float(_b); } while(0)
#define ADD2(d, a, b)  asm("add.rn.f32x2 %0, %1, %2;" : "=l"(d) : "l"(a), "l"(b))
#define MUL2(d, a, b)  asm("mul.rn.f32x2 %0, %1, %2;" : "=l"(d) : "l"(a), "l"(b))
#define FMA2ACC(acc, a, b) asm("fma.rn.f32x2 %0, %1, %2, %0;" : "+l"(acc) : "l"(a), "l"(b))
#define EX2(d, a)      asm("ex2.approx.ftz.f32 %0, %1;" : "=f"(d) : "f"(a))

__global__ __launch_bounds__(192, 2) void alnn_main(
    const float* __restrict__ X, const float* __restrict__ T,
    const float* __restrict__ M, const float* __restrict__ DT,
    const float* __restrict__ P, const float* __restrict__ alpha,
    const float* __restrict__ w_t, const float* __restrict__ b_t,
    const float* __restrict__ w_v)
{
    // Grid: 256 = 4 bg x 8 rg x 8 ls. Block: 192 = 4 lgroups x 48 d.
    const int c  = blockIdx.x;
    const int ls = c & 7;
    const int rg = (c >> 3) & 7;
    const int bg = c >> 6;

    const int tid = threadIdx.x;
    const int d = tid % D_;
    const int g = tid / D_;          // 0..3
    const int b0 = bg * 8;
    const int r0 = rg * 8;
    const int l0 = ls * 16 + g * 4;  // 4 l's per thread

    // Per-r constants
    float naa[8], nrr[8];
#pragma unroll
    for (int ri = 0; ri < 8; ri++) {
        const int r = r0 + ri;
        naa[ri] = -fmaxf(alpha[r], 0.0f) * 1.4426950408889634f; // -relu(alpha)*log2e
        nrr[ri] = -(float)r * (48.0f / 63.0f);
    }

    ull acc2[4][8];
#pragma unroll
    for (int p = 0; p < 4; p++)
#pragma unroll
        for (int ri = 0; ri < 8; ri++) acc2[p][ri] = 0ull;

#pragma unroll 1
    for (int j = 0; j < 4; j++) {
        const int l = l0 + j;

        // Load 8 batches at (l,d), packed into 4 b-pairs
        ull xv2[4], xr2[4], tv2[4], mv2[4], dtv2[4], pv2[4];
#pragma unroll
        for (int p = 0; p < 4; p++) {
            const int i0 = ((b0 + 2*p) * L_ + l) * D_ + d;
            const int i1 = i0 + L_ * D_;
            const float x0 = X[i0], x1 = X[i1];
            PACK2(xv2[p], x0, x1);
            const float xr0 = fmaxf(x0, 0.0f), xr1 = fmaxf(x1, 0.0f);
            PACK2(xr2[p], xr0, xr1);
            PACK2(tv2[p],  T[i0],  T[i1]);
            PACK2(mv2[p],  M[i0],  M[i1]);
            PACK2(dtv2[p], DT[i0], DT[i1]);
            PACK2(pv2[p],  P[i0],  P[i1]);
        }

        const int wbase = (r0 * L_ + l) * D_ + d;
#pragma unroll
        for (int ri = 0; ri < 8; ri++) {
            const int wi = wbase + ri * (L_ * D_);
            const float* wt = w_t + (size_t)wi * 5;
            const float w0 = wt[0], w1 = wt[1], w2 = wt[2], w3 = wt[3], w4 = wt[4];
            const float bt5 = 5.0f * b_t[wi];
            const float wvh = 0.5f * w_v[wi];       // fold relu's 1/2 into w_v (exact)
            ull w0_2, w1_2, w2_2, w3_2, w4_2, bt2, wv2, rr2, aa2;
            PACK2(w0_2, w0, w0);  PACK2(w1_2, w1, w1);
            PACK2(w2_2, w2, w2);  PACK2(w3_2, w3, w3);
            PACK2(w4_2, w4, w4);  PACK2(bt2, bt5, bt5);
            PACK2(wv2, wvh, wvh);
            PACK2(rr2, nrr[ri], nrr[ri]);
            PACK2(aa2, naa[ri], naa[ri]);

#pragma unroll
            for (int p = 0; p < 4; p++) {
                ull d2, m2, k2, i2, s2, hs2;
                ADD2(d2, tv2[p], rr2);                 // t - ref
                MUL2(m2, d2, aa2);                     // -a*(t-ref), sign varies
                ull arg2 = m2 | 0x8000000080000000ull; // -|a*(t-ref)|  (a>=0)
                float e0, e1, k0, k1;
                UNPACK2(e0, e1, arg2);
                EX2(k0, e0); EX2(k1, e1);
                PACK2(k2, k0, k1);
                MUL2(i2, xr2[p], k2);                  // relu(x)*kernel = relu(x*kernel)
                s2 = bt2;
                FMA2ACC(s2, w0_2, xv2[p]);
                FMA2ACC(s2, w1_2, i2);
                FMA2ACC(s2, w2_2, mv2[p]);
                FMA2ACC(s2, w3_2, dtv2[p]);
                FMA2ACC(s2, w4_2, pv2[p]);
                const ull ab2 = s2 & 0x7fffffff7fffffffull;
                ADD2(hs2, s2, ab2);                    // 2*relu(s)
                FMA2ACC(acc2[p][ri], wv2, hs2);        // (w_v/2)*2*relu(s)
            }
        }
    }

    // Intra-CTA reduction over the 4 l-groups, in 2 halves of 4 batches.
    __shared__ float sm[4 * 4 * 8 * D_];   // [g][bl][ri][d] = 24KB
#pragma unroll 1
    for (int h = 0; h < 2; h++) {
#pragma unroll
        for (int bl = 0; bl < 4; bl++) {
            const int p = h * 2 + (bl >> 1);
            const int hi = bl & 1;
#pragma unroll
            for (int ri = 0; ri < 8; ri++) {
                float lo, hv;
                UNPACK2(lo, hv, acc2[p][ri]);
                sm[((g * 4 + bl) * 8 + ri) * D_ + d] = hi ? hv : lo;
            }
        }
        __syncthreads();
#pragma unroll
        for (int k = 0; k < 8; k++) {
            const int idx = k * 192 + tid;             // 0..1535
            const float s = sm[idx] + sm[1536 + idx] + sm[2*1536 + idx] + sm[3*1536 + idx];
            const int dd = idx % D_;
            const int ri = (idx / D_) % 8;
            const int bl = idx / (8 * D_);
            const int b = b0 + h * 4 + bl;
            const int r = r0 + ri;
            g_scratch[ls * OUTSZ + (b * R_ + r) * D_ + dd] = s;
        }
        __syncthreads();
    }
}

__global__ void alnn_finalize(const float* __restrict__ b_v, float* __restrict__ out)
{
    const int gt = blockIdx.x * blockDim.x + threadIdx.x;   // 0..196607
    const int i = gt >> 1;
    const int half = gt & 1;
    float s = 0.0f;
#pragma unroll
    for (int k = 0; k < 4; k++)
        s += g_scratch[(half * 4 + k) * OUTSZ + i];
    s += __shfl_xor_sync(0xffffffffu, s, 1);
    if (half == 0) {
        const int d = i % D_;
        const int r = (i / D_) & (R_ - 1);
        out[i] = fmaxf(fmaf(128.0f, b_v[r * D_ + d], s), 0.0f);
    }
}

extern "C" void kernel_launch(void* const* d_in, const int* in_sizes, int n_in,
                              void* d_out, int out_size)
{
    const float* X     = (const float*)d_in[0];
    const float* T     = (const float*)d_in[1];
    const float* M     = (const float*)d_in[2];
    const float* DT    = (const float*)d_in[3];
    const float* P     = (const float*)d_in[4];
    const float* alpha = (const float*)d_in[5];
    const float* w_t   = (const float*)d_in[6];
    const float* b_t   = (const float*)d_in[7];
    const float* w_v   = (const float*)d_in[8];
    const float* b_v   = (const float*)d_in[9];
    float* out = (float*)d_out;

    alnn_main<<<256, 192>>>(X, T, M, DT, P, alpha, w_t, b_t, w_v);
    alnn_finalize<<<(2 * OUTSZ) / 256, 256>>>(b_v, out);
}